// round 12
// baseline (speedup 1.0000x reference)
#include <cuda_runtime.h>
#include <cuda_fp16.h>

#define NB   8
#define TOUT 256
#define TIN  512
#define LH   128
#define G4   512
#define DIN  128
#define DATT 128

#define OUT_X_ELEMS (NB*TOUT*(LH+DATT))
#define OUT_H_OFF   (OUT_X_ELEMS)
#define OUT_C_OFF   (OUT_X_ELEMS + NB*LH)

// ---- LSTM config: all weights in registers (R10, proven) ----
#define KF32 48
#define KH16 80

// ---- score config: LUT tanh ----
#define KPW  68
#define KP4  17
#define NTAB 1024
#define TAB_SCALE 96.0f                   // entries cover [-5.333, 5.333]
#define TAB_OFF   512.0f
#define S_KEYS_SZ (128 * KPW * 4)         // 34816
#define S_Q_SZ    (8 * 128 * 4)           // 4096 (f32 q)
#define S_W3_SZ   (128 * 4)               // 512
#define S_TAB_SZ  (NTAB * 8)              // 8192 (float2)
#define SCORE_DSMEM (S_KEYS_SZ + S_Q_SZ + S_W3_SZ + S_TAB_SZ)  // 47616

__device__ float  g_xz[NB*TOUT*G4];
__device__ __half g_keys_h[NB*TIN*LH];
__device__ float  g_q[NB*TOUT*LH];
__device__ float  g_sc[NB*TOUT*TIN];

// ---- helpers ----
__device__ __forceinline__ float ex2f(float x) {
    float y; asm("ex2.approx.f32 %0, %1;" : "=f"(y) : "f"(x)); return y;
}
__device__ __forceinline__ float rcpf(float x) {
    float y; asm("rcp.approx.f32 %0, %1;" : "=f"(y) : "f"(x)); return y;
}
__device__ __forceinline__ float tanh_fast(float x) {
    float t = ex2f(x * 2.885390082f);
    return fmaf(-2.0f, rcpf(1.0f + t), 1.0f);
}
__device__ __forceinline__ float sigm_fast(float x) {
    float t = ex2f(x * -1.442695041f);
    return rcpf(1.0f + t);
}
__device__ __forceinline__ __half2 u2h2(unsigned u) {
    __half2 h; *reinterpret_cast<unsigned*>(&h) = u; return h;
}
__device__ __forceinline__ unsigned h22u(__half2 h) {
    return *reinterpret_cast<unsigned*>(&h);
}

// ---------------------------------------------------------------------------
// K1: fused projections (unchanged from R10).
// ---------------------------------------------------------------------------
__global__ void __launch_bounds__(128) proj_kernel(
    const float* __restrict__ att, const float* __restrict__ W1,
    const float* __restrict__ b1,  __half* __restrict__ keys_h,
    const float* __restrict__ inp, const float* __restrict__ Wk,
    const float* __restrict__ lbias, float* __restrict__ xz)
{
    int bid = blockIdx.x;
    int j = threadIdx.x;
    if (bid < 256) {
        __shared__ float a_s[16][DATT];
        int row0 = bid * 16;
        for (int i = j; i < 16 * DATT; i += 128) {
            int r = i >> 7, d = i & 127;
            a_s[r][d] = att[(row0 + r) * DATT + d];
        }
        __syncthreads();
        float acc[16];
        float bj = b1[j];
        #pragma unroll
        for (int r = 0; r < 16; r++) acc[r] = bj;
        for (int l = 0; l < DATT; l++) {
            float wl = W1[l * LH + j];
            #pragma unroll
            for (int r = 0; r < 16; r++)
                acc[r] += a_s[r][l] * wl;
        }
        #pragma unroll
        for (int r = 0; r < 16; r++)
            keys_h[(row0 + r) * LH + j] = __float2half(acc[r]);
    } else {
        __shared__ float a_s[8][DIN];
        int row0 = (bid - 256) * 8;
        for (int i = j; i < 8 * DIN; i += 128) {
            int r = i >> 7, d = i & 127;
            a_s[r][d] = inp[(row0 + r) * DIN + d];
        }
        __syncthreads();
        float acc[4][8];
        #pragma unroll
        for (int c = 0; c < 4; c++) {
            float bc = lbias[j + c * 128];
            #pragma unroll
            for (int r = 0; r < 8; r++) acc[c][r] = bc;
        }
        for (int d = 0; d < DIN; d++) {
            float w0 = Wk[d * G4 + j];
            float w1 = Wk[d * G4 + j + 128];
            float w2 = Wk[d * G4 + j + 256];
            float w3 = Wk[d * G4 + j + 384];
            #pragma unroll
            for (int r = 0; r < 8; r++) {
                float av = a_s[r][d];
                acc[0][r] += av * w0;
                acc[1][r] += av * w1;
                acc[2][r] += av * w2;
                acc[3][r] += av * w3;
            }
        }
        #pragma unroll
        for (int r = 0; r < 8; r++) {
            float* o = xz + (row0 + r) * G4;
            o[j] = acc[0][r]; o[j + 128] = acc[1][r];
            o[j + 256] = acc[2][r]; o[j + 384] = acc[3][r];
        }
    }
}

// ---------------------------------------------------------------------------
// K2: LSTM scan (R10, proven: all weights in registers, f32+f16 split).
// ---------------------------------------------------------------------------
__global__ void __launch_bounds__(512, 1) lstm_kernel(
    const float* __restrict__ xz, const float* __restrict__ Wr,
    float* __restrict__ out)
{
    int b = blockIdx.x;
    int j = threadIdx.x;
    __shared__ __align__(16) float  h_f[LH];
    __shared__ __align__(16) __half h_h[LH];
    __shared__ float z_s[G4];

    float wf[KF32];
    #pragma unroll
    for (int k = 0; k < KF32; k++)
        wf[k] = Wr[k * G4 + j];
    unsigned wh[KH16 / 2];
    #pragma unroll
    for (int p = 0; p < KH16 / 2; p++) {
        __half2 v = __floats2half2_rn(Wr[(KF32 + 2 * p) * G4 + j],
                                      Wr[(KF32 + 2 * p + 1) * G4 + j]);
        wh[p] = h22u(v);
    }

    if (j < LH) {
        h_f[j] = 0.0f;
        h_h[j] = __float2half(0.0f);
    }
    float c = 0.0f;
    __syncthreads();

    const float* xzb = xz + b * TOUT * G4;
    float xnext = xzb[j];
    bool is_g = (j >= 2 * LH) && (j < 3 * LH);

    for (int t = 0; t < TOUT; t++) {
        float acc0 = xnext;
        float acc1 = 0.0f;
        if (t + 1 < TOUT) xnext = xzb[(t + 1) * G4 + j];

        #pragma unroll
        for (int kk = 0; kk < KF32 / 4; kk++) {
            float4 h4 = *reinterpret_cast<const float4*>(&h_f[kk * 4]);
            acc0 += h4.x * wf[kk * 4 + 0];
            acc1 += h4.y * wf[kk * 4 + 1];
            acc0 += h4.z * wf[kk * 4 + 2];
            acc1 += h4.w * wf[kk * 4 + 3];
        }
        const unsigned* hh = reinterpret_cast<const unsigned*>(&h_h[KF32]);
        #pragma unroll
        for (int ch = 0; ch < 5; ch++) {
            __half2 a = __floats2half2_rn(0.f, 0.f);
            #pragma unroll
            for (int i = 0; i < 8; i++) {
                int p = ch * 8 + i;
                a = __hfma2(u2h2(hh[p]), u2h2(wh[p]), a);
            }
            float2 f = __half22float2(a);
            acc0 += f.x;
            acc1 += f.y;
        }
        float z = acc0 + acc1;
        z_s[j] = is_g ? tanh_fast(z) : sigm_fast(z);
        __syncthreads();
        if (j < LH) {
            c = z_s[LH + j] * c + z_s[j] * z_s[2 * LH + j];
            float h = z_s[3 * LH + j] * tanh_fast(c);
            h_f[j] = h;
            h_h[j] = __float2half(h);
            out[(b * TOUT + t) * (LH + DATT) + j] = h;
        }
        __syncthreads();
    }
    if (j < LH) {
        out[OUT_H_OFF + b * LH + j] = h_f[j];
        out[OUT_C_OFF + b * LH + j] = c;
    }
}

// ---------------------------------------------------------------------------
// K3: q = x @ W2 + b2 -> f32.
// ---------------------------------------------------------------------------
__global__ void __launch_bounds__(128) q_kernel(
    const float* __restrict__ out, const float* __restrict__ W2,
    const float* __restrict__ b2, float* __restrict__ q)
{
    int row0 = blockIdx.x * 16;
    int j = threadIdx.x;
    __shared__ float x_s[16][LH];
    for (int i = j; i < 16 * LH; i += 128) {
        int r = i >> 7, l = i & 127;
        x_s[r][l] = out[(row0 + r) * (LH + DATT) + l];
    }
    __syncthreads();
    float acc[16];
    float bj = b2[j];
    #pragma unroll
    for (int r = 0; r < 16; r++) acc[r] = bj;
    for (int l = 0; l < LH; l++) {
        float wl = W2[l * LH + j];
        #pragma unroll
        for (int r = 0; r < 16; r++)
            acc[r] += x_s[r][l] * wl;
    }
    #pragma unroll
    for (int r = 0; r < 16; r++)
        q[(row0 + r) * LH + j] = acc[r];
}

// ---------------------------------------------------------------------------
// K4: raw scores via smem tanh LUT — ZERO MUFU in the hot loop.
//     table: 1024 (value, slope) pairs over [-5.333, 5.333], linear interp.
// ---------------------------------------------------------------------------
#define TANHLUT(z, dst) {                                                  \
    float _t = fminf(fmaxf(fmaf((z), TAB_SCALE, TAB_OFF), 0.0f), 1023.0f); \
    float _f = floorf(_t);                                                 \
    float2 _e = tab[(int)_f];                                              \
    dst = fmaf(_e.y, _t - _f, _e.x); }

#define SCLUT(kc, q0v, q1v, w0v, w1v, acc) {                               \
    float2 _kf = __half22float2(u2h2(kc));                                 \
    float _th;                                                             \
    TANHLUT(_kf.x + (q0v), _th);                                           \
    acc = fmaf((w0v), _th, acc);                                           \
    TANHLUT(_kf.y + (q1v), _th);                                           \
    acc = fmaf((w1v), _th, acc); }

__global__ void __launch_bounds__(256) score_kernel(
    const __half* __restrict__ keys_h_g, const float* __restrict__ q_g,
    const float* __restrict__ W3, float* __restrict__ sc_g)
{
    extern __shared__ char sm[];
    uint4*  keyv = reinterpret_cast<uint4*>(sm);                   // [128][KP4]
    float*  qf   = reinterpret_cast<float*>(sm + S_KEYS_SZ);       // [8][128]
    float*  w3f  = reinterpret_cast<float*>(sm + S_KEYS_SZ + S_Q_SZ); // [128]
    float2* tab  = reinterpret_cast<float2*>(sm + S_KEYS_SZ + S_Q_SZ + S_W3_SZ);

    int b  = blockIdx.z;
    int q0 = blockIdx.y * 8;
    int k0 = blockIdx.x * 128;
    int tid = threadIdx.x;

    // build tanh table (4 entries/thread)
    #pragma unroll
    for (int i = tid; i < NTAB; i += 256) {
        float x  = (i - 512) * (1.0f / TAB_SCALE);
        float v  = tanh_fast(x);
        float v1 = tanh_fast(x + (1.0f / TAB_SCALE));
        tab[i] = make_float2(v, v1 - v);
    }
    // stage keys (half2, stride KP4 uint4)
    const uint4* kg = reinterpret_cast<const uint4*>(keys_h_g + (b * TIN + k0) * LH);
    for (int i = tid; i < 128 * 16; i += 256) {
        int k = i >> 4, cc = i & 15;
        keyv[k * KP4 + cc] = kg[k * 16 + cc];
    }
    // stage q (f32) and w3
    {
        int r = tid >> 5, cc = tid & 31;
        *reinterpret_cast<float4*>(&qf[r * 128 + cc * 4]) =
            *reinterpret_cast<const float4*>(q_g + (b * TOUT + q0 + r) * LH + cc * 4);
    }
    if (tid < 32)
        *reinterpret_cast<float4*>(&w3f[tid * 4]) =
            *reinterpret_cast<const float4*>(W3 + tid * 4);
    __syncthreads();

    int ql = tid >> 5;            // warp-uniform q row
    int kk = tid & 31;            // chains kk, +32, +64, +96
    const float* qrow = qf + ql * 128;

    float f0 = 0.f, f1 = 0.f, f2 = 0.f, f3 = 0.f;
    #pragma unroll 4
    for (int g = 0; g < 16; g++) {
        float4 qa = *reinterpret_cast<const float4*>(&qrow[g * 8]);
        float4 qb = *reinterpret_cast<const float4*>(&qrow[g * 8 + 4]);
        float4 wa = *reinterpret_cast<const float4*>(&w3f[g * 8]);
        float4 wb = *reinterpret_cast<const float4*>(&w3f[g * 8 + 4]);
        uint4 kA = keyv[kk * KP4 + g];
        uint4 kB = keyv[(kk + 32) * KP4 + g];
        uint4 kC = keyv[(kk + 64) * KP4 + g];
        uint4 kD = keyv[(kk + 96) * KP4 + g];
        SCLUT(kA.x, qa.x, qa.y, wa.x, wa.y, f0);
        SCLUT(kB.x, qa.x, qa.y, wa.x, wa.y, f1);
        SCLUT(kC.x, qa.x, qa.y, wa.x, wa.y, f2);
        SCLUT(kD.x, qa.x, qa.y, wa.x, wa.y, f3);
        SCLUT(kA.y, qa.z, qa.w, wa.z, wa.w, f0);
        SCLUT(kB.y, qa.z, qa.w, wa.z, wa.w, f1);
        SCLUT(kC.y, qa.z, qa.w, wa.z, wa.w, f2);
        SCLUT(kD.y, qa.z, qa.w, wa.z, wa.w, f3);
        SCLUT(kA.z, qb.x, qb.y, wb.x, wb.y, f0);
        SCLUT(kB.z, qb.x, qb.y, wb.x, wb.y, f1);
        SCLUT(kC.z, qb.x, qb.y, wb.x, wb.y, f2);
        SCLUT(kD.z, qb.x, qb.y, wb.x, wb.y, f3);
        SCLUT(kA.w, qb.z, qb.w, wb.z, wb.w, f0);
        SCLUT(kB.w, qb.z, qb.w, wb.z, wb.w, f1);
        SCLUT(kC.w, qb.z, qb.w, wb.z, wb.w, f2);
        SCLUT(kD.w, qb.z, qb.w, wb.z, wb.w, f3);
    }
    float* orow = sc_g + (b * TOUT + q0 + ql) * TIN + k0;
    orow[kk]      = f0;
    orow[kk + 32] = f1;
    orow[kk + 64] = f2;
    orow[kk + 96] = f3;
}

// ---------------------------------------------------------------------------
// K5: fused softmax + weighted (proven).
// ---------------------------------------------------------------------------
__global__ void __launch_bounds__(256) weighted_kernel(
    const float* __restrict__ sc_g, const float* __restrict__ att,
    float* __restrict__ out)
{
    int b  = blockIdx.y;
    int q0 = blockIdx.x * 16;
    int tid = threadIdx.x;

    __shared__ float a_s[16][TIN];
    for (int i = tid; i < 16 * TIN; i += 256) {
        int r = i >> 9, kk = i & 511;
        a_s[r][kk] = sc_g[(b * TOUT + q0 + r) * TIN + kk];
    }
    __syncthreads();

    int w = tid >> 5, lane = tid & 31;
    for (int r = w; r < 16; r += 8) {
        float* row = a_s[r];
        float v[16], mx = -1e30f;
        #pragma unroll
        for (int i = 0; i < 16; i++) {
            v[i] = row[lane + 32 * i];
            mx = fmaxf(mx, v[i]);
        }
        #pragma unroll
        for (int off = 16; off >= 1; off >>= 1)
            mx = fmaxf(mx, __shfl_xor_sync(0xffffffffu, mx, off));
        float s = 0.0f;
        #pragma unroll
        for (int i = 0; i < 16; i++) {
            v[i] = ex2f((v[i] - mx) * 1.442695041f);
            s += v[i];
        }
        #pragma unroll
        for (int off = 16; off >= 1; off >>= 1)
            s += __shfl_xor_sync(0xffffffffu, s, off);
        float inv = rcpf(s);
        #pragma unroll
        for (int i = 0; i < 16; i++)
            row[lane + 32 * i] = v[i] * inv;
    }
    __syncthreads();

    int d = tid & 127;
    int g = tid >> 7;
    float acc[8];
    #pragma unroll
    for (int i = 0; i < 8; i++) acc[i] = 0.0f;

    const float* ap = att + b * TIN * DATT + d;
    #pragma unroll 4
    for (int k = 0; k < TIN; k++) {
        float av = ap[k * DATT];
        #pragma unroll
        for (int i = 0; i < 8; i++)
            acc[i] += a_s[g * 8 + i][k] * av;
    }
    #pragma unroll
    for (int i = 0; i < 8; i++)
        out[(b * TOUT + q0 + g * 8 + i) * (LH + DATT) + LH + d] = acc[i];
}

// ---------------------------------------------------------------------------
extern "C" void kernel_launch(void* const* d_in, const int* in_sizes, int n_in,
                              void* d_out, int out_size)
{
    const float* inputs   = (const float*)d_in[0];
    const float* attended = (const float*)d_in[1];
    const float* Wk       = (const float*)d_in[2];
    const float* Wr       = (const float*)d_in[3];
    const float* lbias    = (const float*)d_in[4];
    const float* W1       = (const float*)d_in[5];
    const float* b1       = (const float*)d_in[6];
    const float* W2       = (const float*)d_in[7];
    const float* b2       = (const float*)d_in[8];
    const float* W3       = (const float*)d_in[9];
    float* out = (float*)d_out;

    cudaFuncSetAttribute(score_kernel,
                         cudaFuncAttributeMaxDynamicSharedMemorySize, SCORE_DSMEM);

    proj_kernel<<<512, 128>>>(attended, W1, b1, g_keys_h,
                              inputs, Wk, lbias, g_xz);
    lstm_kernel<<<NB, 512>>>(g_xz, Wr, out);
    q_kernel<<<NB * TOUT / 16, 128>>>(out, W2, b2, g_q);
    {
        dim3 grid(TIN / 128, TOUT / 8, NB);
        score_kernel<<<grid, 256, SCORE_DSMEM>>>(g_keys_h, g_q, W3, g_sc);
    }
    {
        dim3 grid(16, NB);
        weighted_kernel<<<grid, 256>>>(g_sc, attended, out);
    }
    (void)in_sizes; (void)n_in; (void)out_size;
}